// round 1
// baseline (speedup 1.0000x reference)
#include <cuda_runtime.h>
#include <cuda_bf16.h>

// Problem constants
#define BB   512
#define LL   16384
#define WSZ  5
#define NW   (LL - WSZ + 1)     // 16380 windows

// Tiling
#define TPB  128                // threads per block
#define WPT  8                  // windows per thread
#define CW   (TPB * WPT)        // 1024 windows per block (x-dim)
#define NWCH ((NW + CW - 1) / CW)   // 16 window chunks
#define BC   8                  // batches per block (y-dim)
#define NBCH (BB / BC)          // 64 batch chunks

// Deterministic scratch (no cudaMalloc allowed): per-(batch-chunk, window) partials.
__device__ float g_sq_part[(size_t)NBCH * NW];   // sum over chunk's batches of (pvar-tvar)^2
__device__ float g_ms_part[(size_t)NBCH * NW];   // sum over chunk's batches of msum
__device__ float g_red_sum[64];
__device__ float g_red_cnt[64];

__global__ __launch_bounds__(TPB)
void bcl_main(const float* __restrict__ pred,
              const int*   __restrict__ tgt,
              const int*   __restrict__ msk)
{
    const int w0  = blockIdx.x * CW + threadIdx.x * WPT;  // first window of this thread
    if (w0 >= NW) return;
    const int bch = blockIdx.y;
    const int b0  = bch * BC;

    float acc_sq[WPT], acc_ms[WPT];
#pragma unroll
    for (int k = 0; k < WPT; k++) { acc_sq[k] = 0.f; acc_ms[k] = 0.f; }

    const bool fast = (w0 + WPT + 4 <= LL);   // full vector-load path in bounds

    for (int bi = 0; bi < BC; bi++) {
        const int b = b0 + bi;
        const float* pr = pred + (size_t)b * LL * 2;
        const int*   tr = tgt  + (size_t)b * LL;
        const int*   mr = msk  + (size_t)b * LL;

        float x0[WPT + 4], x1[WPT + 4];
        int   tt[WPT + 4], mm[WPT + 4];

        if (fast) {
            const float4* p4 = reinterpret_cast<const float4*>(pr + 2 * w0);
#pragma unroll
            for (int i = 0; i < (WPT + 4) / 2; i++) {
                float4 v = p4[i];
                x0[2*i]   = v.x; x1[2*i]   = v.y;
                x0[2*i+1] = v.z; x1[2*i+1] = v.w;
            }
            const int4* t4 = reinterpret_cast<const int4*>(tr + w0);
            const int4* m4 = reinterpret_cast<const int4*>(mr + w0);
#pragma unroll
            for (int i = 0; i < (WPT + 4) / 4; i++) {
                int4 tv = t4[i]; int4 mv = m4[i];
                tt[4*i] = tv.x; tt[4*i+1] = tv.y; tt[4*i+2] = tv.z; tt[4*i+3] = tv.w;
                mm[4*i] = mv.x; mm[4*i+1] = mv.y; mm[4*i+2] = mv.z; mm[4*i+3] = mv.w;
            }
        } else {
            // Only the very last thread of the last window-chunk lands here.
#pragma unroll
            for (int e = 0; e < WPT + 4; e++) {
                int idx = w0 + e;
                if (idx < LL) {
                    x0[e] = pr[2*idx]; x1[e] = pr[2*idx + 1];
                    tt[e] = tr[idx];   mm[e] = mr[idx];
                } else { x0[e] = 0.f; x1[e] = 0.f; tt[e] = 0; mm[e] = 0; }
            }
        }

        // Per-element masked quantities. softmax(x)[...,1] == sigmoid(x1-x0).
        float qm[WPT + 4], qpm[WPT + 4], qtm[WPT + 4], qp2[WPT + 4];
#pragma unroll
        for (int e = 0; e < WPT + 4; e++) {
            float mf = (float)mm[e];
            float tf = (float)tt[e];
            float p  = __fdividef(1.0f, 1.0f + __expf(x0[e] - x1[e]));
            qm[e]  = mf;
            qpm[e] = p * mf;
            qtm[e] = tf * mf;
            qp2[e] = p * p * mf;
        }

        // Sliding window-5 sums, incremental across the 8 windows of this thread.
        float sm = qm[0]  + qm[1]  + qm[2]  + qm[3]  + qm[4];
        float sp = qpm[0] + qpm[1] + qpm[2] + qpm[3] + qpm[4];
        float st = qtm[0] + qtm[1] + qtm[2] + qtm[3] + qtm[4];
        float s2 = qp2[0] + qp2[1] + qp2[2] + qp2[3] + qp2[4];
#pragma unroll
        for (int k = 0; k < WPT; k++) {
            if (k > 0) {
                sm += qm[k+4]  - qm[k-1];
                sp += qpm[k+4] - qpm[k-1];
                st += qtm[k+4] - qtm[k-1];
                s2 += qp2[k+4] - qp2[k-1];
            }
            // denom = max(msum,1); msum is integer-valued, so:
            //   pvar = sp2m/denom - pmean^2 ; tvar = tmean*(1-tmean)
            float denom = fmaxf(sm, 1.0f);
            float rd    = __fdividef(1.0f, denom);
            float pmean = sp * rd;
            float tmean = st * rd;
            float pvar  = s2 * rd - pmean * pmean;
            float tvar  = tmean - tmean * tmean;
            float d     = pvar - tvar;
            acc_sq[k] += d * d;
            acc_ms[k] += sm;
        }
    }

    // Deterministic partial writeout (no float atomics).
#pragma unroll
    for (int k = 0; k < WPT; k++) {
        int j = w0 + k;
        if (j < NW) {
            g_sq_part[(size_t)bch * NW + j] = acc_sq[k];
            g_ms_part[(size_t)bch * NW + j] = acc_ms[k];
        }
    }
}

// Stage 1: per-window combine across batch chunks; per-block partial (sum, count).
__global__ void bcl_reduce1()
{
    __shared__ float ss[256], sc[256];
    const int j = blockIdx.x * 256 + threadIdx.x;
    float s = 0.f, c = 0.f;
    if (j < NW) {
        float sq = 0.f, ms = 0.f;
#pragma unroll 4
        for (int ch = 0; ch < NBCH; ch++) {
            sq += g_sq_part[(size_t)ch * NW + j];
            ms += g_ms_part[(size_t)ch * NW + j];
        }
        if (ms > 0.f) { s = sq * (1.0f / (float)BB); c = 1.f; }
    }
    ss[threadIdx.x] = s; sc[threadIdx.x] = c;
    __syncthreads();
    for (int o = 128; o > 0; o >>= 1) {
        if (threadIdx.x < o) {
            ss[threadIdx.x] += ss[threadIdx.x + o];
            sc[threadIdx.x] += sc[threadIdx.x + o];
        }
        __syncthreads();
    }
    if (threadIdx.x == 0) {
        g_red_sum[blockIdx.x] = ss[0];
        g_red_cnt[blockIdx.x] = sc[0];
    }
}

// Stage 2: final scalar. loss = sum(mse*valid)/max(cnt,1) * CONSISTENCY_WEIGHT(=1)
__global__ void bcl_reduce2(float* __restrict__ out)
{
    __shared__ float ss[64], sc[64];
    ss[threadIdx.x] = g_red_sum[threadIdx.x];
    sc[threadIdx.x] = g_red_cnt[threadIdx.x];
    __syncthreads();
    for (int o = 32; o > 0; o >>= 1) {
        if (threadIdx.x < o) {
            ss[threadIdx.x] += ss[threadIdx.x + o];
            sc[threadIdx.x] += sc[threadIdx.x + o];
        }
        __syncthreads();
    }
    if (threadIdx.x == 0)
        out[0] = ss[0] / fmaxf(sc[0], 1.0f);
}

extern "C" void kernel_launch(void* const* d_in, const int* in_sizes, int n_in,
                              void* d_out, int out_size)
{
    const float* pred = (const float*)d_in[0];   // [512, 16384, 2] f32
    const int*   tgt  = (const int*)d_in[1];     // [512, 16384] i32
    const int*   msk  = (const int*)d_in[2];     // [512, 16384] i32

    dim3 grid(NWCH, NBCH);                        // 16 x 64 = 1024 blocks
    bcl_main<<<grid, TPB>>>(pred, tgt, msk);
    bcl_reduce1<<<64, 256>>>();
    bcl_reduce2<<<1, 64>>>((float*)d_out);
}

// round 2
// speedup vs baseline: 1.2080x; 1.2080x over previous
#include <cuda_runtime.h>
#include <cuda_bf16.h>

// Problem constants
#define BB   512
#define LL   16384
#define WSZ  5
#define NW   (LL - WSZ + 1)         // 16380 windows

// Tiling
#define TPB  128
#define WPT  8
#define CW   (TPB * WPT)            // 1024 windows per block
#define NWCH ((NW + CW - 1) / CW)   // 16 window chunks
#define BC   8                      // batches per block
#define NBCH (BB / BC)              // 64 batch chunks
#define NGRP (NWCH * TPB)           // 2048 window-groups (8 windows each)

// Deterministic scratch (no cudaMalloc allowed).
__device__ float    g_sq_part[(size_t)NBCH * NW];    // per-(chunk,window) sum of (pvar-tvar)^2
__device__ unsigned g_valid[(size_t)NBCH * NGRP];    // per-(chunk,group) 8-bit validity mask
__device__ float    g_red_sum[128];
__device__ float    g_red_cnt[128];

__global__ __launch_bounds__(TPB, 8)
void bcl_main(const float* __restrict__ pred,
              const int*   __restrict__ tgt,
              const int*   __restrict__ msk)
{
    const int tid = threadIdx.x;
    const int w0  = blockIdx.x * CW + tid * WPT;     // first window of this thread
    const int bch = blockIdx.y;
    const int b0  = bch * BC;

    float acc[WPT];
#pragma unroll
    for (int k = 0; k < WPT; k++) acc[k] = 0.f;
    unsigned vmask = 0u;

    const bool fast = (w0 + WPT + 4 <= LL);          // full vector path in bounds

    for (int bi = 0; bi < BC; bi++) {
        const int b = b0 + bi;
        const float* pr = pred + (size_t)b * LL * 2;
        const int*   tr = tgt  + (size_t)b * LL;
        const int*   mr = msk  + (size_t)b * LL;

        float p[WPT + 4];    // sigmoid probabilities
        float mf[WPT + 4];   // mask as float
        float tmf[WPT + 4];  // target*mask as float

        if (fast) {
            float4 v[6];
            const float4* p4 = reinterpret_cast<const float4*>(pr + 2 * w0);
#pragma unroll
            for (int i = 0; i < 6; i++) v[i] = p4[i];
            int4 tv[3], mv[3];
            const int4* t4 = reinterpret_cast<const int4*>(tr + w0);
            const int4* m4 = reinterpret_cast<const int4*>(mr + w0);
#pragma unroll
            for (int i = 0; i < 3; i++) { tv[i] = t4[i]; mv[i] = m4[i]; }
#pragma unroll
            for (int i = 0; i < 6; i++) {
                // softmax(x)[...,1] == sigmoid(x1-x0)
                p[2*i]   = __fdividef(1.0f, 1.0f + __expf(v[i].x - v[i].y));
                p[2*i+1] = __fdividef(1.0f, 1.0f + __expf(v[i].z - v[i].w));
            }
#pragma unroll
            for (int i = 0; i < 3; i++) {
                mf[4*i]   = (float)mv[i].x; mf[4*i+1] = (float)mv[i].y;
                mf[4*i+2] = (float)mv[i].z; mf[4*i+3] = (float)mv[i].w;
                tmf[4*i]   = (float)tv[i].x * mf[4*i];
                tmf[4*i+1] = (float)tv[i].y * mf[4*i+1];
                tmf[4*i+2] = (float)tv[i].z * mf[4*i+2];
                tmf[4*i+3] = (float)tv[i].w * mf[4*i+3];
            }
        } else {
            // Only one thread per batch-chunk (last window group) lands here.
#pragma unroll
            for (int e = 0; e < WPT + 4; e++) {
                int idx = w0 + e;
                if (idx < LL) {
                    p[e]   = __fdividef(1.0f, 1.0f + __expf(pr[2*idx] - pr[2*idx+1]));
                    mf[e]  = (float)mr[idx];
                    tmf[e] = (float)tr[idx] * mf[e];
                } else { p[e] = 0.f; mf[e] = 0.f; tmf[e] = 0.f; }
            }
        }

        // Sliding window-5 sums, incremental. pm / p^2 m recomputed to save regs.
        float sm = mf[0]  + mf[1]  + mf[2]  + mf[3]  + mf[4];
        float st = tmf[0] + tmf[1] + tmf[2] + tmf[3] + tmf[4];
        float sp = p[0]*mf[0] + p[1]*mf[1] + p[2]*mf[2] + p[3]*mf[3] + p[4]*mf[4];
        float s2 = p[0]*p[0]*mf[0] + p[1]*p[1]*mf[1] + p[2]*p[2]*mf[2]
                 + p[3]*p[3]*mf[3] + p[4]*p[4]*mf[4];
#pragma unroll
        for (int k = 0; k < WPT; k++) {
            if (k > 0) {
                float pa = p[k+4], ma = mf[k+4];
                float pb = p[k-1], mb = mf[k-1];
                sm += ma - mb;
                st += tmf[k+4] - tmf[k-1];
                sp += pa*ma - pb*mb;
                s2 += pa*pa*ma - pb*pb*mb;
            }
            // msum integer-valued: pvar = s2/denom - pmean^2 ; tvar = tmean(1-tmean)
            float denom = fmaxf(sm, 1.0f);
            float rd    = __fdividef(1.0f, denom);
            float pmean = sp * rd;
            float tmean = st * rd;
            float d     = (s2 * rd - pmean * pmean) - (tmean - tmean * tmean);
            acc[k] += d * d;
            if (sm > 0.f) vmask |= (1u << k);
        }
    }

    // Deterministic partial writeout.
    const unsigned base = (unsigned)bch * NW + (unsigned)w0;
#pragma unroll
    for (int k = 0; k < WPT; k++)
        if (w0 + k < NW) g_sq_part[base + k] = acc[k];
    g_valid[(unsigned)bch * NGRP + blockIdx.x * TPB + tid] = vmask;
}

// Stage 1: per-window combine across batch chunks; per-block partial (sum, count).
__global__ __launch_bounds__(128)
void bcl_reduce1()
{
    __shared__ float ss[128], sc[128];
    const int j = blockIdx.x * 128 + threadIdx.x;   // window index
    float s = 0.f, c = 0.f;
    if (j < NW) {
        float sq = 0.f;
        unsigned v = 0u;
        const int grp = j >> 3;
        const int bit = j & 7;
#pragma unroll 8
        for (int ch = 0; ch < NBCH; ch++) {
            sq += g_sq_part[(unsigned)ch * NW + j];
            v  |= g_valid[(unsigned)ch * NGRP + grp];
        }
        if ((v >> bit) & 1u) { s = sq * (1.0f / (float)BB); c = 1.f; }
    }
    ss[threadIdx.x] = s; sc[threadIdx.x] = c;
    __syncthreads();
    for (int o = 64; o > 0; o >>= 1) {
        if (threadIdx.x < o) {
            ss[threadIdx.x] += ss[threadIdx.x + o];
            sc[threadIdx.x] += sc[threadIdx.x + o];
        }
        __syncthreads();
    }
    if (threadIdx.x == 0) {
        g_red_sum[blockIdx.x] = ss[0];
        g_red_cnt[blockIdx.x] = sc[0];
    }
}

// Stage 2: final scalar. loss = sum(mse*valid)/max(cnt,1) * CONSISTENCY_WEIGHT(=1)
__global__ __launch_bounds__(128)
void bcl_reduce2(float* __restrict__ out)
{
    __shared__ float ss[128], sc[128];
    ss[threadIdx.x] = g_red_sum[threadIdx.x];
    sc[threadIdx.x] = g_red_cnt[threadIdx.x];
    __syncthreads();
    for (int o = 64; o > 0; o >>= 1) {
        if (threadIdx.x < o) {
            ss[threadIdx.x] += ss[threadIdx.x + o];
            sc[threadIdx.x] += sc[threadIdx.x + o];
        }
        __syncthreads();
    }
    if (threadIdx.x == 0)
        out[0] = ss[0] / fmaxf(sc[0], 1.0f);
}

extern "C" void kernel_launch(void* const* d_in, const int* in_sizes, int n_in,
                              void* d_out, int out_size)
{
    const float* pred = (const float*)d_in[0];   // [512, 16384, 2] f32
    const int*   tgt  = (const int*)d_in[1];     // [512, 16384] i32
    const int*   msk  = (const int*)d_in[2];     // [512, 16384] i32

    dim3 grid(NWCH, NBCH);                        // 16 x 64 = 1024 blocks, one wave @ 8 blk/SM
    bcl_main<<<grid, TPB>>>(pred, tgt, msk);
    bcl_reduce1<<<128, 128>>>();
    bcl_reduce2<<<1, 128>>>((float*)d_out);
}

// round 3
// speedup vs baseline: 1.2874x; 1.0658x over previous
#include <cuda_runtime.h>
#include <cuda_bf16.h>

// Problem constants
#define BB   512
#define LL   16384
#define NW   (LL - 5 + 1)          // 16380 windows
#define NWP  16384                 // padded window stride

// Tiling
#define TPB  128                   // 4 warps
#define SEGW 128                   // windows (=elements) per warp
#define CW   512                   // windows per block
#define NWCH (LL / CW)             // 32 window chunks
#define BC   16                    // batches per block
#define NBCH (BB / BC)             // 32 batch chunks
#define NWG  (LL / SEGW)           // 128 warp-groups along L

// Deterministic scratch (no cudaMalloc allowed).
__device__ float    g_sq_part[(size_t)NBCH * NWP];      // 2 MiB of partials
__device__ unsigned g_vld[(size_t)NBCH * NWG * 4];      // ballot-packed validity
__device__ float    g_red_sum[128];
__device__ float    g_red_cnt[128];

__device__ __forceinline__ float sigm(float x0, float x1) {
    // softmax(x)[...,1] == sigmoid(x1-x0) == 1/(1+exp(x0-x1))
    return __fdividef(1.0f, 1.0f + __expf(x0 - x1));
}

// Per-window math. smm = packed sliding sum (msum + 32*tsum), spm = sum(p*m),
// sq = sum(p^2*m). msum integer-valued => pvar = sq/denom - pmean^2,
// tvar = tmean*(1-tmean). Exactly matches reference up to f32 rounding.
#define WIN(K, ACC) { \
    float stm   = floorf(smm * 0.03125f); \
    float sm    = fmaf(-32.0f, stm, smm); \
    float denom = fmaxf(sm, 1.0f); \
    float rd    = __fdividef(1.0f, denom); \
    float pmean = spm * rd; \
    float tmean = stm * rd; \
    float pvar  = fmaf(-pmean, pmean, sq * rd); \
    float tvar  = fmaf(-tmean, tmean, tmean); \
    float d     = pvar - tvar; \
    ACC = fmaf(d, d, ACC); \
    if (sm > 0.0f) vmask |= (1u << (K)); \
}

__global__ __launch_bounds__(TPB, 7)
void bcl_main(const float* __restrict__ pred,
              const int*   __restrict__ tgt,
              const int*   __restrict__ msk)
{
    const int lane = threadIdx.x & 31;
    const int wrp  = threadIdx.x >> 5;
    const int seg  = blockIdx.x * CW + wrp * SEGW;  // warp's first element/window
    const int bch  = blockIdx.y;
    const bool has_halo = (seg + SEGW) < LL;        // next 4 elems exist?
    const int hofs = has_halo ? (SEGW / 4) : 0;     // int4/2xfloat4 halo offset

    float acc0 = 0.f, acc1 = 0.f, acc2 = 0.f, acc3 = 0.f;
    unsigned vmask = 0u;

    for (int bi = 0; bi < BC; bi++) {
        const int b = bch * BC + bi;
        const size_t eb = (size_t)b * LL + seg;
        const float4* fp4 = (const float4*)(pred + 2 * eb);
        const int4*   t4p = (const int4*)(tgt + eb);
        const int4*   m4p = (const int4*)(msk + eb);

        // Own loads: lane owns elems seg+4*lane .. +3 (coalesced, 32B/16B stride)
        float4 v0 = fp4[2 * lane];
        float4 v1 = fp4[2 * lane + 1];
        int4   tv = t4p[lane];
        int4   mv = m4p[lane];
        // Halo loads (broadcast address; used only by lane 31)
        float4 h0 = fp4[2 * hofs];
        float4 h1 = fp4[2 * hofs + 1];
        int4   htv = t4p[hofs];
        int4   hmv = m4p[hofs];
        if (!has_halo) { hmv.x = 0; hmv.y = 0; hmv.z = 0; hmv.w = 0; }

        // Own derived quantities per element:
        //   mm = m + 32*(t&m)  (packed, one I2F)
        //   pm = m ? p : 0 ;  q = p*pm = p^2*m
        float p0 = sigm(v0.x, v0.y), p1 = sigm(v0.z, v0.w);
        float p2 = sigm(v1.x, v1.y), p3 = sigm(v1.z, v1.w);
        float mm0 = (float)(mv.x + ((tv.x & mv.x) << 5));
        float mm1 = (float)(mv.y + ((tv.y & mv.y) << 5));
        float mm2 = (float)(mv.z + ((tv.z & mv.z) << 5));
        float mm3 = (float)(mv.w + ((tv.w & mv.w) << 5));
        float pm0 = mv.x ? p0 : 0.f, pm1 = mv.y ? p1 : 0.f;
        float pm2 = mv.z ? p2 : 0.f, pm3 = mv.w ? p3 : 0.f;
        float q0 = p0 * pm0, q1 = p1 * pm1, q2 = p2 * pm2, q3 = p3 * pm3;

        // Neighbor (lane+1) quantities via shfl; convergent, before any branch.
        float nmm0 = __shfl_down_sync(0xffffffffu, mm0, 1);
        float nmm1 = __shfl_down_sync(0xffffffffu, mm1, 1);
        float nmm2 = __shfl_down_sync(0xffffffffu, mm2, 1);
        float nmm3 = __shfl_down_sync(0xffffffffu, mm3, 1);
        float npm0 = __shfl_down_sync(0xffffffffu, pm0, 1);
        float npm1 = __shfl_down_sync(0xffffffffu, pm1, 1);
        float npm2 = __shfl_down_sync(0xffffffffu, pm2, 1);
        float npm3 = __shfl_down_sync(0xffffffffu, pm3, 1);
        float nq0  = __shfl_down_sync(0xffffffffu, q0, 1);
        float nq1  = __shfl_down_sync(0xffffffffu, q1, 1);
        float nq2  = __shfl_down_sync(0xffffffffu, q2, 1);
        float nq3  = __shfl_down_sync(0xffffffffu, q3, 1);

        if (lane == 31) {
            // Patch halo from broadcast loads (zeros if no halo -> mask gated).
            float hp0 = sigm(h0.x, h0.y), hp1 = sigm(h0.z, h0.w);
            float hp2 = sigm(h1.x, h1.y), hp3 = sigm(h1.z, h1.w);
            nmm0 = (float)(hmv.x + ((htv.x & hmv.x) << 5));
            nmm1 = (float)(hmv.y + ((htv.y & hmv.y) << 5));
            nmm2 = (float)(hmv.z + ((htv.z & hmv.z) << 5));
            nmm3 = (float)(hmv.w + ((htv.w & hmv.w) << 5));
            npm0 = hmv.x ? hp0 : 0.f; npm1 = hmv.y ? hp1 : 0.f;
            npm2 = hmv.z ? hp2 : 0.f; npm3 = hmv.w ? hp3 : 0.f;
            nq0 = hp0 * npm0; nq1 = hp1 * npm1; nq2 = hp2 * npm2; nq3 = hp3 * npm3;
        }

        // Sliding window-5 sums over {own0..3, n0..3}, incremental.
        float smm = mm0 + mm1 + mm2 + mm3 + nmm0;
        float spm = pm0 + pm1 + pm2 + pm3 + npm0;
        float sq  = q0 + q1 + q2 + q3 + nq0;
        WIN(0, acc0)
        smm += nmm1 - mm0; spm += npm1 - pm0; sq += nq1 - q0;
        WIN(1, acc1)
        smm += nmm2 - mm1; spm += npm2 - pm1; sq += nq2 - q1;
        WIN(2, acc2)
        smm += nmm3 - mm2; spm += npm3 - pm2; sq += nq3 - q2;
        WIN(3, acc3)
    }

    // Coalesced partial writeout (float4 per lane) + ballot-packed validity.
    ((float4*)(g_sq_part + (size_t)bch * NWP + seg))[lane] =
        make_float4(acc0, acc1, acc2, acc3);

    unsigned b0 = __ballot_sync(0xffffffffu, (vmask >> 0) & 1u);
    unsigned b1 = __ballot_sync(0xffffffffu, (vmask >> 1) & 1u);
    unsigned b2 = __ballot_sync(0xffffffffu, (vmask >> 2) & 1u);
    unsigned b3 = __ballot_sync(0xffffffffu, (vmask >> 3) & 1u);
    if (lane == 0) {
        const int wg = seg / SEGW;
        *((uint4*)(g_vld + ((size_t)bch * NWG + wg) * 4)) = make_uint4(b0, b1, b2, b3);
    }
}

// Stage 1: per-window combine across batch chunks.
__global__ __launch_bounds__(128)
void bcl_reduce1()
{
    __shared__ float ss[128], sc[128];
    const int j = blockIdx.x * 128 + threadIdx.x;   // window index
    float s = 0.f, c = 0.f;
    if (j < NW) {
        float sq = 0.f;
        unsigned any = 0u;
        const int widx = ((j >> 7) << 2) + (j & 3); // word within a chunk's 512
        const int bit  = (j >> 2) & 31;
#pragma unroll 8
        for (int ch = 0; ch < NBCH; ch++) {
            sq  += g_sq_part[(size_t)ch * NWP + j];
            any |= g_vld[(size_t)ch * (NWG * 4) + widx];
        }
        if ((any >> bit) & 1u) { s = sq * (1.0f / (float)BB); c = 1.f; }
    }
    ss[threadIdx.x] = s; sc[threadIdx.x] = c;
    __syncthreads();
    for (int o = 64; o > 0; o >>= 1) {
        if (threadIdx.x < o) {
            ss[threadIdx.x] += ss[threadIdx.x + o];
            sc[threadIdx.x] += sc[threadIdx.x + o];
        }
        __syncthreads();
    }
    if (threadIdx.x == 0) {
        g_red_sum[blockIdx.x] = ss[0];
        g_red_cnt[blockIdx.x] = sc[0];
    }
}

// Stage 2: loss = sum(mse*valid)/max(cnt,1) * CONSISTENCY_WEIGHT(=1)
__global__ __launch_bounds__(128)
void bcl_reduce2(float* __restrict__ out)
{
    __shared__ float ss[128], sc[128];
    ss[threadIdx.x] = g_red_sum[threadIdx.x];
    sc[threadIdx.x] = g_red_cnt[threadIdx.x];
    __syncthreads();
    for (int o = 64; o > 0; o >>= 1) {
        if (threadIdx.x < o) {
            ss[threadIdx.x] += ss[threadIdx.x + o];
            sc[threadIdx.x] += sc[threadIdx.x + o];
        }
        __syncthreads();
    }
    if (threadIdx.x == 0)
        out[0] = ss[0] / fmaxf(sc[0], 1.0f);
}

extern "C" void kernel_launch(void* const* d_in, const int* in_sizes, int n_in,
                              void* d_out, int out_size)
{
    const float* pred = (const float*)d_in[0];   // [512, 16384, 2] f32
    const int*   tgt  = (const int*)d_in[1];     // [512, 16384] i32
    const int*   msk  = (const int*)d_in[2];     // [512, 16384] i32

    dim3 grid(NWCH, NBCH);                        // 32 x 32 = 1024 blocks
    bcl_main<<<grid, TPB>>>(pred, tgt, msk);
    bcl_reduce1<<<128, 128>>>();
    bcl_reduce2<<<1, 128>>>((float*)d_out);
}

// round 4
// speedup vs baseline: 1.3010x; 1.0105x over previous
#include <cuda_runtime.h>
#include <cuda_bf16.h>

// Problem constants
#define BB   512
#define LL   16384
#define NW   (LL - 5 + 1)          // 16380 windows

// Tiling
#define TPB  128                   // 4 warps
#define SEGW 128                   // windows (=elements) per warp
#define CW   512                   // windows per block
#define NWCH (LL / CW)             // 32 window chunks
#define BC   8                     // batches per block
#define NBCH (BB / BC)             // 64 batch chunks
#define NWG  (LL / SEGW)           // 128 warp-groups along L
#define NBLK (NWCH * NBCH)         // 2048 blocks

// Deterministic scratch (no cudaMalloc allowed).
__device__ float    g_sq_blk[NBLK];                 // one sq partial per block
__device__ unsigned g_vld[(size_t)NBCH * NWG * 4];  // ballot-packed validity (128 KB)

__device__ __forceinline__ float sigm(float x0, float x1) {
    // softmax(x)[...,1] == sigmoid(x1-x0) == 1/(1+exp(x0-x1))
    return __fdividef(1.0f, 1.0f + __expf(x0 - x1));
}

// Per-window math. smm = packed sliding sum (msum + 32*tsum), spm = sum(p*m),
// sq = sum(p^2*m). msum integer-valued => pvar = sq/denom - pmean^2,
// tvar = tmean*(1-tmean). Matches reference up to f32 rounding.
#define WIN(K, ACC) { \
    float stm   = floorf(smm * 0.03125f); \
    float sm    = fmaf(-32.0f, stm, smm); \
    float denom = fmaxf(sm, 1.0f); \
    float rd    = __fdividef(1.0f, denom); \
    float pmean = spm * rd; \
    float tmean = stm * rd; \
    float pvar  = fmaf(-pmean, pmean, sq * rd); \
    float tvar  = fmaf(-tmean, tmean, tmean); \
    float d     = pvar - tvar; \
    ACC = fmaf(d, d, ACC); \
    if (sm > 0.0f) vmask |= (1u << (K)); \
}

__global__ __launch_bounds__(TPB, 8)
void bcl_main(const float* __restrict__ pred,
              const int*   __restrict__ tgt,
              const int*   __restrict__ msk)
{
    const int lane = threadIdx.x & 31;
    const int wrp  = threadIdx.x >> 5;
    const int seg  = blockIdx.x * CW + wrp * SEGW;  // warp's first element/window
    const int bch  = blockIdx.y;
    const bool has_halo = (seg + SEGW) < LL;        // next 4 elems exist?
    const int hofs = has_halo ? (SEGW / 4) : 0;     // int4/2xfloat4 halo offset
    const int w    = seg + 4 * lane;                // lane's first window

    float acc0 = 0.f, acc1 = 0.f, acc2 = 0.f, acc3 = 0.f;
    unsigned vmask = 0u;

    for (int bi = 0; bi < BC; bi++) {
        const int b = bch * BC + bi;
        const size_t eb = (size_t)b * LL + seg;
        const float4* fp4 = (const float4*)(pred + 2 * eb);
        const int4*   t4p = (const int4*)(tgt + eb);
        const int4*   m4p = (const int4*)(msk + eb);

        // Own loads: lane owns elems seg+4*lane .. +3 (32B/16B lane stride)
        float4 v0 = fp4[2 * lane];
        float4 v1 = fp4[2 * lane + 1];
        int4   tv = t4p[lane];
        int4   mv = m4p[lane];
        // Halo loads (broadcast address; used only by lane 31)
        float4 h0 = fp4[2 * hofs];
        float4 h1 = fp4[2 * hofs + 1];
        int4   htv = t4p[hofs];
        int4   hmv = m4p[hofs];
        if (!has_halo) { hmv.x = 0; hmv.y = 0; hmv.z = 0; hmv.w = 0; }

        // Derived per-element: mm = m + 32*(t&m); pm = p*m; q = p^2*m
        float p0 = sigm(v0.x, v0.y), p1 = sigm(v0.z, v0.w);
        float p2 = sigm(v1.x, v1.y), p3 = sigm(v1.z, v1.w);
        float mm0 = (float)(mv.x + ((tv.x & mv.x) << 5));
        float mm1 = (float)(mv.y + ((tv.y & mv.y) << 5));
        float mm2 = (float)(mv.z + ((tv.z & mv.z) << 5));
        float mm3 = (float)(mv.w + ((tv.w & mv.w) << 5));
        float pm0 = mv.x ? p0 : 0.f, pm1 = mv.y ? p1 : 0.f;
        float pm2 = mv.z ? p2 : 0.f, pm3 = mv.w ? p3 : 0.f;
        float q0 = p0 * pm0, q1 = p1 * pm1, q2 = p2 * pm2, q3 = p3 * pm3;

        // Neighbor (lane+1) quantities via shfl; convergent, before any branch.
        float nmm0 = __shfl_down_sync(0xffffffffu, mm0, 1);
        float nmm1 = __shfl_down_sync(0xffffffffu, mm1, 1);
        float nmm2 = __shfl_down_sync(0xffffffffu, mm2, 1);
        float nmm3 = __shfl_down_sync(0xffffffffu, mm3, 1);
        float npm0 = __shfl_down_sync(0xffffffffu, pm0, 1);
        float npm1 = __shfl_down_sync(0xffffffffu, pm1, 1);
        float npm2 = __shfl_down_sync(0xffffffffu, pm2, 1);
        float npm3 = __shfl_down_sync(0xffffffffu, pm3, 1);
        float nq0  = __shfl_down_sync(0xffffffffu, q0, 1);
        float nq1  = __shfl_down_sync(0xffffffffu, q1, 1);
        float nq2  = __shfl_down_sync(0xffffffffu, q2, 1);
        float nq3  = __shfl_down_sync(0xffffffffu, q3, 1);

        if (lane == 31) {
            // Patch halo from broadcast loads (mask-gated zeros if no halo).
            float hp0 = sigm(h0.x, h0.y), hp1 = sigm(h0.z, h0.w);
            float hp2 = sigm(h1.x, h1.y), hp3 = sigm(h1.z, h1.w);
            nmm0 = (float)(hmv.x + ((htv.x & hmv.x) << 5));
            nmm1 = (float)(hmv.y + ((htv.y & hmv.y) << 5));
            nmm2 = (float)(hmv.z + ((htv.z & hmv.z) << 5));
            nmm3 = (float)(hmv.w + ((htv.w & hmv.w) << 5));
            npm0 = hmv.x ? hp0 : 0.f; npm1 = hmv.y ? hp1 : 0.f;
            npm2 = hmv.z ? hp2 : 0.f; npm3 = hmv.w ? hp3 : 0.f;
            nq0 = hp0 * npm0; nq1 = hp1 * npm1; nq2 = hp2 * npm2; nq3 = hp3 * npm3;
        }

        // Sliding window-5 sums over {own0..3, n0..3}, incremental.
        float smm = mm0 + mm1 + mm2 + mm3 + nmm0;
        float spm = pm0 + pm1 + pm2 + pm3 + npm0;
        float sq  = q0 + q1 + q2 + q3 + nq0;
        WIN(0, acc0)
        smm += nmm1 - mm0; spm += npm1 - pm0; sq += nq1 - q0;
        WIN(1, acc1)
        smm += nmm2 - mm1; spm += npm2 - pm1; sq += nq2 - q1;
        WIN(2, acc2)
        smm += nmm3 - mm2; spm += npm3 - pm2; sq += nq3 - q2;
        WIN(3, acc3)
    }

    // Gate off windows >= NW (only lane 31 of the last warp) — invalid windows
    // contribute 0 to sq by construction elsewhere, but these read OOB-zeroed
    // halo and must be excluded from both sq and validity.
    unsigned amask = 0u;
    if (w + 0 < NW) amask |= 1u; else acc0 = 0.f;
    if (w + 1 < NW) amask |= 2u; else acc1 = 0.f;
    if (w + 2 < NW) amask |= 4u; else acc2 = 0.f;
    if (w + 3 < NW) amask |= 8u; else acc3 = 0.f;
    vmask &= amask;

    // Ballot-packed validity writeout (one uint4 per warp).
    unsigned b0 = __ballot_sync(0xffffffffu, (vmask >> 0) & 1u);
    unsigned b1 = __ballot_sync(0xffffffffu, (vmask >> 1) & 1u);
    unsigned b2 = __ballot_sync(0xffffffffu, (vmask >> 2) & 1u);
    unsigned b3 = __ballot_sync(0xffffffffu, (vmask >> 3) & 1u);
    if (lane == 0) {
        const int wg = seg / SEGW;
        *((uint4*)(g_vld + ((size_t)bch * NWG + wg) * 4)) = make_uint4(b0, b1, b2, b3);
    }

    // In-block deterministic reduction of sq -> one float per block.
    float a = (acc0 + acc1) + (acc2 + acc3);
    a += __shfl_xor_sync(0xffffffffu, a, 16);
    a += __shfl_xor_sync(0xffffffffu, a, 8);
    a += __shfl_xor_sync(0xffffffffu, a, 4);
    a += __shfl_xor_sync(0xffffffffu, a, 2);
    a += __shfl_xor_sync(0xffffffffu, a, 1);
    __shared__ float s_red[4];
    if (lane == 0) s_red[wrp] = a;
    __syncthreads();
    if (threadIdx.x == 0)
        g_sq_blk[bch * NWCH + blockIdx.x] =
            (s_red[0] + s_red[1]) + (s_red[2] + s_red[3]);
}

// Fused final reduce: sum 2048 block partials + popcount OR'd validity.
__global__ __launch_bounds__(512)
void bcl_reduce(float* __restrict__ out)
{
    __shared__ float ssq[512];
    __shared__ int   scn[512];
    const int t = threadIdx.x;

    float s = g_sq_blk[t] + g_sq_blk[t + 512]
            + g_sq_blk[t + 1024] + g_sq_blk[t + 1536];

    unsigned v = 0u;
#pragma unroll 8
    for (int ch = 0; ch < NBCH; ch++)
        v |= g_vld[(size_t)ch * 512 + t];
    int c = __popc(v);

    ssq[t] = s; scn[t] = c;
    __syncthreads();
    for (int o = 256; o > 0; o >>= 1) {
        if (t < o) { ssq[t] += ssq[t + o]; scn[t] += scn[t + o]; }
        __syncthreads();
    }
    if (t == 0)
        out[0] = ssq[0] * (1.0f / (float)BB) / fmaxf((float)scn[0], 1.0f);
}

extern "C" void kernel_launch(void* const* d_in, const int* in_sizes, int n_in,
                              void* d_out, int out_size)
{
    const float* pred = (const float*)d_in[0];   // [512, 16384, 2] f32
    const int*   tgt  = (const int*)d_in[1];     // [512, 16384] i32
    const int*   msk  = (const int*)d_in[2];     // [512, 16384] i32

    dim3 grid(NWCH, NBCH);                        // 32 x 64 = 2048 blocks
    bcl_main<<<grid, TPB>>>(pred, tgt, msk);
    bcl_reduce<<<1, 512>>>((float*)d_out);
}

// round 5
// speedup vs baseline: 1.3705x; 1.0535x over previous
#include <cuda_runtime.h>
#include <cuda_bf16.h>

// Problem constants
#define BB   512
#define LL   16384
#define NW   (LL - 5 + 1)          // 16380 windows

// Tiling
#define TPB  128                   // 4 warps
#define SEGW 128                   // windows (=elements) per warp
#define CW   512                   // windows per block
#define NWCH (LL / CW)             // 32 window chunks
#define BC   8                     // batches per block
#define NBCH (BB / BC)             // 64 batch chunks
#define NWG  (LL / SEGW)           // 128 warp-groups along L
#define NBLK (NWCH * NBCH)         // 2048 blocks
#define NVW  (NWG * 4)             // 512 validity words (1 bit per window)

// Deterministic scratch (no cudaMalloc allowed).
__device__ float    g_sq_blk[NBLK];     // one sq partial per block (8 KB)
__device__ unsigned g_vld_or[NVW];      // OR-accumulated validity bits (2 KB)

__device__ __forceinline__ float sigm(float x0, float x1) {
    // softmax(x)[...,1] == sigmoid(x1-x0) == 1/(1+exp(x0-x1))
    return __fdividef(1.0f, 1.0f + __expf(x0 - x1));
}

// Per-window math. smm = packed sliding sum (msum + 32*tsum), spm = sum(p*m),
// sq = sum(p^2*m). msum integer-valued => pvar = sq/denom - pmean^2,
// tvar = tmean*(1-tmean). Matches reference up to f32 rounding.
#define WIN(K, ACC) { \
    float stm   = floorf(smm * 0.03125f); \
    float sm    = fmaf(-32.0f, stm, smm); \
    float denom = fmaxf(sm, 1.0f); \
    float rd    = __fdividef(1.0f, denom); \
    float pmean = spm * rd; \
    float tmean = stm * rd; \
    float pvar  = fmaf(-pmean, pmean, sq * rd); \
    float tvar  = fmaf(-tmean, tmean, tmean); \
    float d     = pvar - tvar; \
    ACC = fmaf(d, d, ACC); \
    if (sm > 0.0f) vmask |= (1u << (K)); \
}

// Zero the OR-accumulator (RED.OR accumulates across graph replays).
__global__ __launch_bounds__(NVW)
void bcl_init()
{
    g_vld_or[threadIdx.x] = 0u;
}

__global__ __launch_bounds__(TPB, 8)
void bcl_main(const float* __restrict__ pred,
              const int*   __restrict__ tgt,
              const int*   __restrict__ msk)
{
    const int lane = threadIdx.x & 31;
    const int wrp  = threadIdx.x >> 5;
    const int seg  = blockIdx.x * CW + wrp * SEGW;  // warp's first element/window
    const int bch  = blockIdx.y;
    const bool has_halo = (seg + SEGW) < LL;        // next 4 elems exist?
    const int hofs = has_halo ? (SEGW / 4) : 0;     // int4/2xfloat4 halo offset
    const int w    = seg + 4 * lane;                // lane's first window

    float acc0 = 0.f, acc1 = 0.f, acc2 = 0.f, acc3 = 0.f;
    unsigned vmask = 0u;

    for (int bi = 0; bi < BC; bi++) {
        const int b = bch * BC + bi;
        const size_t eb = (size_t)b * LL + seg;
        const float4* fp4 = (const float4*)(pred + 2 * eb);
        const int4*   t4p = (const int4*)(tgt + eb);
        const int4*   m4p = (const int4*)(msk + eb);

        // Own loads: lane owns elems seg+4*lane .. +3 (32B/16B lane stride)
        float4 v0 = fp4[2 * lane];
        float4 v1 = fp4[2 * lane + 1];
        int4   tv = t4p[lane];
        int4   mv = m4p[lane];
        // Halo loads (broadcast address; used only by lane 31)
        float4 h0 = fp4[2 * hofs];
        float4 h1 = fp4[2 * hofs + 1];
        int4   htv = t4p[hofs];
        int4   hmv = m4p[hofs];
        if (!has_halo) { hmv.x = 0; hmv.y = 0; hmv.z = 0; hmv.w = 0; }

        // Derived per-element: mm = m + 32*(t&m); pm = p*m; q = p^2*m
        float p0 = sigm(v0.x, v0.y), p1 = sigm(v0.z, v0.w);
        float p2 = sigm(v1.x, v1.y), p3 = sigm(v1.z, v1.w);
        float mm0 = (float)(mv.x + ((tv.x & mv.x) << 5));
        float mm1 = (float)(mv.y + ((tv.y & mv.y) << 5));
        float mm2 = (float)(mv.z + ((tv.z & mv.z) << 5));
        float mm3 = (float)(mv.w + ((tv.w & mv.w) << 5));
        float pm0 = mv.x ? p0 : 0.f, pm1 = mv.y ? p1 : 0.f;
        float pm2 = mv.z ? p2 : 0.f, pm3 = mv.w ? p3 : 0.f;
        float q0 = p0 * pm0, q1 = p1 * pm1, q2 = p2 * pm2, q3 = p3 * pm3;

        // Neighbor (lane+1) quantities via shfl; convergent, before any branch.
        float nmm0 = __shfl_down_sync(0xffffffffu, mm0, 1);
        float nmm1 = __shfl_down_sync(0xffffffffu, mm1, 1);
        float nmm2 = __shfl_down_sync(0xffffffffu, mm2, 1);
        float nmm3 = __shfl_down_sync(0xffffffffu, mm3, 1);
        float npm0 = __shfl_down_sync(0xffffffffu, pm0, 1);
        float npm1 = __shfl_down_sync(0xffffffffu, pm1, 1);
        float npm2 = __shfl_down_sync(0xffffffffu, pm2, 1);
        float npm3 = __shfl_down_sync(0xffffffffu, pm3, 1);
        float nq0  = __shfl_down_sync(0xffffffffu, q0, 1);
        float nq1  = __shfl_down_sync(0xffffffffu, q1, 1);
        float nq2  = __shfl_down_sync(0xffffffffu, q2, 1);
        float nq3  = __shfl_down_sync(0xffffffffu, q3, 1);

        if (lane == 31) {
            // Patch halo from broadcast loads (mask-gated zeros if no halo).
            float hp0 = sigm(h0.x, h0.y), hp1 = sigm(h0.z, h0.w);
            float hp2 = sigm(h1.x, h1.y), hp3 = sigm(h1.z, h1.w);
            nmm0 = (float)(hmv.x + ((htv.x & hmv.x) << 5));
            nmm1 = (float)(hmv.y + ((htv.y & hmv.y) << 5));
            nmm2 = (float)(hmv.z + ((htv.z & hmv.z) << 5));
            nmm3 = (float)(hmv.w + ((htv.w & hmv.w) << 5));
            npm0 = hmv.x ? hp0 : 0.f; npm1 = hmv.y ? hp1 : 0.f;
            npm2 = hmv.z ? hp2 : 0.f; npm3 = hmv.w ? hp3 : 0.f;
            nq0 = hp0 * npm0; nq1 = hp1 * npm1; nq2 = hp2 * npm2; nq3 = hp3 * npm3;
        }

        // Sliding window-5 sums over {own0..3, n0..3}, incremental.
        float smm = mm0 + mm1 + mm2 + mm3 + nmm0;
        float spm = pm0 + pm1 + pm2 + pm3 + npm0;
        float sq  = q0 + q1 + q2 + q3 + nq0;
        WIN(0, acc0)
        smm += nmm1 - mm0; spm += npm1 - pm0; sq += nq1 - q0;
        WIN(1, acc1)
        smm += nmm2 - mm1; spm += npm2 - pm1; sq += nq2 - q1;
        WIN(2, acc2)
        smm += nmm3 - mm2; spm += npm3 - pm2; sq += nq3 - q2;
        WIN(3, acc3)
    }

    // Gate off windows >= NW (only lane 31 of the last warp) — they read
    // OOB-zeroed halo and must be excluded from both sq and validity.
    unsigned amask = 0u;
    if (w + 0 < NW) amask |= 1u; else acc0 = 0.f;
    if (w + 1 < NW) amask |= 2u; else acc1 = 0.f;
    if (w + 2 < NW) amask |= 4u; else acc2 = 0.f;
    if (w + 3 < NW) amask |= 8u; else acc3 = 0.f;
    vmask &= amask;

    // Validity: ballot-pack, then OR into the global per-window bit array.
    // Integer atomicOr is order-independent -> deterministic.
    unsigned b0 = __ballot_sync(0xffffffffu, (vmask >> 0) & 1u);
    unsigned b1 = __ballot_sync(0xffffffffu, (vmask >> 1) & 1u);
    unsigned b2 = __ballot_sync(0xffffffffu, (vmask >> 2) & 1u);
    unsigned b3 = __ballot_sync(0xffffffffu, (vmask >> 3) & 1u);
    if (lane == 0) {
        const int wg = seg / SEGW;
        atomicOr(&g_vld_or[wg * 4 + 0], b0);
        atomicOr(&g_vld_or[wg * 4 + 1], b1);
        atomicOr(&g_vld_or[wg * 4 + 2], b2);
        atomicOr(&g_vld_or[wg * 4 + 3], b3);
    }

    // In-block deterministic reduction of sq -> one float per block.
    float a = (acc0 + acc1) + (acc2 + acc3);
    a += __shfl_xor_sync(0xffffffffu, a, 16);
    a += __shfl_xor_sync(0xffffffffu, a, 8);
    a += __shfl_xor_sync(0xffffffffu, a, 4);
    a += __shfl_xor_sync(0xffffffffu, a, 2);
    a += __shfl_xor_sync(0xffffffffu, a, 1);
    __shared__ float s_red[4];
    if (lane == 0) s_red[wrp] = a;
    __syncthreads();
    if (threadIdx.x == 0)
        g_sq_blk[bch * NWCH + blockIdx.x] =
            (s_red[0] + s_red[1]) + (s_red[2] + s_red[3]);
}

// Final reduce: sum 2048 block partials (8 KB) + popcount validity (2 KB).
__global__ __launch_bounds__(512)
void bcl_reduce(float* __restrict__ out)
{
    __shared__ float ssq[512];
    __shared__ int   scn[512];
    const int t = threadIdx.x;

    float s = (g_sq_blk[t] + g_sq_blk[t + 512])
            + (g_sq_blk[t + 1024] + g_sq_blk[t + 1536]);
    int c = __popc(g_vld_or[t]);

    ssq[t] = s; scn[t] = c;
    __syncthreads();
    for (int o = 256; o > 0; o >>= 1) {
        if (t < o) { ssq[t] += ssq[t + o]; scn[t] += scn[t + o]; }
        __syncthreads();
    }
    if (t == 0)
        out[0] = ssq[0] * (1.0f / (float)BB) / fmaxf((float)scn[0], 1.0f);
}

extern "C" void kernel_launch(void* const* d_in, const int* in_sizes, int n_in,
                              void* d_out, int out_size)
{
    const float* pred = (const float*)d_in[0];   // [512, 16384, 2] f32
    const int*   tgt  = (const int*)d_in[1];     // [512, 16384] i32
    const int*   msk  = (const int*)d_in[2];     // [512, 16384] i32

    bcl_init<<<1, NVW>>>();
    dim3 grid(NWCH, NBCH);                        // 32 x 64 = 2048 blocks
    bcl_main<<<grid, TPB>>>(pred, tgt, msk);
    bcl_reduce<<<1, 512>>>((float*)d_out);
}